// round 9
// baseline (speedup 1.0000x reference)
#include <cuda_runtime.h>
#include <cuda_bf16.h>
#include <math.h>
#include <stdint.h>

typedef unsigned long long ULL;
typedef unsigned int u32;

#define H 40
#define W 40
#define CIN 2048
#define CMID 256
#define NPIX 1600
#define NANCH 8000
#define MAXDET 300
#define NWORDS 250          // 8000/32
#define NMSBATCH 8

__device__ __constant__ float c_anchor[5] = {32.f, 64.f, 128.f, 256.f, 512.f};

// ---------------- device scratch (static; no allocation) ----------------
__device__ float  g_partial[9 * NPIX * CMID];   // per-tap conv partials
__device__ float  g_scores[NANCH];
__device__ float4 g_boxes[NANCH];
__device__ float4 g_boxes_sorted[NANCH];
__device__ u32    g_mask[NANCH * NWORDS];       // suppression bitmap rows (8MB)
__device__ float  g_rois[MAXDET * 4];

// =====================================================================
// Kernel 0: no-op x3 so the profiler's fixed 4th-launch capture lands
// on conv3x3_partial (diagnostic).
// =====================================================================
__global__ void nop_kernel() {}

// =====================================================================
// Kernel 1: tap-split implicit GEMM.  grid (25, 4, 9), 64 threads.
// Block tile 64 pixels x 64 couts, per-thread 8x8, fma.rn.f32x2.
// Double-buffered smem (1 barrier/chunk); A gather coalesced 4-lanes-
// per-pixel (8 lines/warp-LDG).  K accumulation order identical to all
// prior rounds -> bit-identical partials.
// =====================================================================
__global__ __launch_bounds__(64, 7) void conv3x3_partial(
    const float* __restrict__ feat, const float* __restrict__ w)
{
    const int mt = blockIdx.x, nt = blockIdx.y, tap = blockIdx.z;
    const int dy = tap / 3 - 1, dx = tap % 3 - 1;
    const int m0 = mt * 64, n0 = nt * 64;
    const int tid = threadIdx.x;

    __shared__ float Asf[2][16][68];   // [stage][k][pixel]
    __shared__ float Bsf[2][16][68];   // [stage][k][cout]

    // ---- A loader mapping: j in 0..3 -> pixel (tid>>2)+16j, k-quarter tid&3
    const int aq = tid & 3;            // k sub-quarter (4 floats)
    const float* aptr[4];
    bool avalid[4];
    int apl[4];
#pragma unroll
    for (int j = 0; j < 4; j++) {
        int pl = (tid >> 2) + 16 * j;
        apl[j] = pl;
        int p = m0 + pl;
        int py = p / W, px = p - py * W;
        int sy = py + dy, sx = px + dx;
        bool v = (sx >= 0) && (sx < W) && (sy >= 0) && (sy < H);
        avalid[j] = v;
        aptr[j] = feat + ((size_t)(v ? (sy * W + sx) : 0) * CIN + aq * 4);
    }

    // ---- B loader mapping: j in 0..3 -> k-row (tid>>4)+4j, col4 tid&15
    const int bc4 = tid & 15;
    const float* bptr = w + ((size_t)(tap * CIN + (tid >> 4)) * CMID + n0 + bc4 * 4);

    // ---- compute mapping: 8 m-groups x 8 n-groups
    const int mg = tid >> 3, ng = tid & 7;

    ULL acc[8][4];
#pragma unroll
    for (int i = 0; i < 8; i++)
#pragma unroll
        for (int j = 0; j < 4; j++) acc[i][j] = 0ull;

    float4 ar[4], br[4];
    // load chunk 0
#pragma unroll
    for (int j = 0; j < 4; j++)
        ar[j] = avalid[j] ? *(const float4*)(aptr[j]) : make_float4(0.f, 0.f, 0.f, 0.f);
#pragma unroll
    for (int j = 0; j < 4; j++)
        br[j] = *(const float4*)(bptr + (size_t)(4 * j) * CMID);
    // STS chunk 0 -> stage 0
#pragma unroll
    for (int j = 0; j < 4; j++) {
        float v[4] = {ar[j].x, ar[j].y, ar[j].z, ar[j].w};
#pragma unroll
        for (int i = 0; i < 4; i++) Asf[0][aq * 4 + i][apl[j]] = v[i];
        *(float4*)&Bsf[0][(tid >> 4) + 4 * j][bc4 * 4] = br[j];
    }
    // load chunk 1 (in flight across the barrier)
#pragma unroll
    for (int j = 0; j < 4; j++)
        ar[j] = avalid[j] ? *(const float4*)(aptr[j] + 16) : make_float4(0.f, 0.f, 0.f, 0.f);
#pragma unroll
    for (int j = 0; j < 4; j++)
        br[j] = *(const float4*)(bptr + (size_t)16 * CMID + (size_t)(4 * j) * CMID);
    __syncthreads();

    const int NCHUNK = CIN / 16;       // 128
    for (int c = 0; c < NCHUNK; c++) {
        const int s = c & 1;

        // compute 16 kc from stage s
#pragma unroll
        for (int kc = 0; kc < 16; kc++) {
            float4 a0 = *(const float4*)&Asf[s][kc][mg * 8 + 0];
            float4 a1 = *(const float4*)&Asf[s][kc][mg * 8 + 4];
            ulonglong2 b03 = *(const ulonglong2*)&Bsf[s][kc][ng * 8 + 0];
            ulonglong2 b47 = *(const ulonglong2*)&Bsf[s][kc][ng * 8 + 4];
            ULL bq[4] = {b03.x, b03.y, b47.x, b47.y};
            float am[8] = {a0.x, a0.y, a0.z, a0.w, a1.x, a1.y, a1.z, a1.w};
#pragma unroll
            for (int mm = 0; mm < 8; mm++) {
                u32 au = __float_as_uint(am[mm]);
                ULL a2;
                asm("mov.b64 %0, {%1, %1};" : "=l"(a2) : "r"(au));
#pragma unroll
                for (int q = 0; q < 4; q++)
                    asm("fma.rn.f32x2 %0, %1, %2, %0;"
                        : "+l"(acc[mm][q]) : "l"(a2), "l"(bq[q]));
            }
        }

        // stage chunk c+1 into the other buffer; start LDG of chunk c+2
        if (c + 1 < NCHUNK) {
#pragma unroll
            for (int j = 0; j < 4; j++) {
                float v[4] = {ar[j].x, ar[j].y, ar[j].z, ar[j].w};
#pragma unroll
                for (int i = 0; i < 4; i++) Asf[s ^ 1][aq * 4 + i][apl[j]] = v[i];
                *(float4*)&Bsf[s ^ 1][(tid >> 4) + 4 * j][bc4 * 4] = br[j];
            }
            if (c + 2 < NCHUNK) {
                const int off = (c + 2) * 16;
#pragma unroll
                for (int j = 0; j < 4; j++)
                    ar[j] = avalid[j] ? *(const float4*)(aptr[j] + off)
                                      : make_float4(0.f, 0.f, 0.f, 0.f);
#pragma unroll
                for (int j = 0; j < 4; j++)
                    br[j] = *(const float4*)(bptr + (size_t)off * CMID + (size_t)(4 * j) * CMID);
            }
        }
        __syncthreads();
    }

    // store partials (each ULL = 2 consecutive fp32 couts)
#pragma unroll
    for (int mm = 0; mm < 8; mm++) {
        int mrow = m0 + mg * 8 + mm;
        size_t base = ((size_t)tap * NPIX + mrow) * CMID + n0 + ng * 8;
        ulonglong2 lo, hi;
        lo.x = acc[mm][0]; lo.y = acc[mm][1];
        hi.x = acc[mm][2]; hi.y = acc[mm][3];
        *(ulonglong2*)&g_partial[base + 0] = lo;
        *(ulonglong2*)&g_partial[base + 4] = hi;
    }
}

// =====================================================================
// Kernel 2: tap-reduce + bias + relu + 1x1 heads + decode, 16 PIXELS
// PER BLOCK.  grid 100, 256 threads.
// =====================================================================
__global__ __launch_bounds__(256) void reduce_heads(
    const float* __restrict__ conv_b,
    const float* __restrict__ cls_w, const float* __restrict__ cls_b,
    const float* __restrict__ reg_w, const float* __restrict__ reg_b)
{
    const int px0 = blockIdx.x * 16;
    const int tid = threadIdx.x;
    const int wid = tid >> 5, lid = tid & 31;
    __shared__ float ws[30 * 256];      // [o][k]  30KB
    __shared__ float xs[16][256];       // 16KB
    __shared__ float ob[16][30];

    for (int idx = tid; idx < 10 * 256; idx += 256) {   // cls_w is [k][10]
        int k = idx / 10, o = idx - k * 10;
        ws[o * 256 + k] = cls_w[idx];
    }
    for (int idx = tid; idx < 20 * 256; idx += 256) {   // reg_w is [k][20]
        int k = idx / 20, o = idx - k * 20;
        ws[(10 + o) * 256 + k] = reg_w[idx];
    }

    for (int e = tid; e < 16 * 256; e += 256) {
        int pp = e >> 8, n = e & 255;
        int pgl = px0 + pp;
        float s = conv_b[n];
#pragma unroll
        for (int t = 0; t < 9; t++)
            s += g_partial[((size_t)t * NPIX + pgl) * CMID + n];
        xs[pp][n] = fmaxf(s, 0.f);
    }
    __syncthreads();

    for (int task = wid; task < 480; task += 8) {
        int pp = task / 30, o = task - pp * 30;
        float bias = (o < 10) ? cls_b[o] : reg_b[o - 10];
        const float* wrow = &ws[o * 256];
        const float* xrow = xs[pp];
        float s = 0.f;
#pragma unroll
        for (int k = lid; k < 256; k += 32)
            s += xrow[k] * wrow[k];
#pragma unroll
        for (int off = 16; off > 0; off >>= 1)
            s += __shfl_xor_sync(0xFFFFFFFFu, s, off);
        if (lid == 0) ob[pp][o] = s + bias;
    }
    __syncthreads();

    if (tid < 80) {
        const int pp = tid / 5, a = tid - pp * 5;
        const int p = px0 + pp;
        float l0 = ob[pp][2 * a], l1 = ob[pp][2 * a + 1];
        float score = 1.f / (1.f + expf(l0 - l1));
        float d0 = ob[pp][10 + 4 * a + 0];
        float d1 = ob[pp][10 + 4 * a + 1];
        float d2 = ob[pp][10 + 4 * a + 2];
        float d3 = ob[pp][10 + 4 * a + 3];
        float px = (float)(p % W), py = (float)(p / W);
        float base = c_anchor[a];
        float bw = expf(d2) * base;
        float bh = expf(d3) * base;
        float xc = px + d0, yc = py + d1;
        g_scores[p * 5 + a] = score;
        g_boxes[p * 5 + a] = make_float4(xc - 0.5f * bw, yc - 0.5f * bh,
                                         xc + 0.5f * bw, yc + 0.5f * bh);
    }
}

// =====================================================================
// Kernel 3: descending bitonic sort, warp-shuffle tail stages.
// =====================================================================
__device__ __forceinline__ ULL warp_cx(ULL key, int lane, int i, int j, int k)
{
    ULL partner = __shfl_xor_sync(0xFFFFFFFFu, key, j);
    bool up = ((lane & j) == 0);
    bool desc = ((i & k) == 0);
    bool take_max = (up == desc);
    ULL mx = key > partner ? key : partner;
    ULL mn = key > partner ? partner : key;
    return take_max ? mx : mn;
}

__global__ void sort_kernel()
{
    extern __shared__ ULL sk[];
    const int tid = threadIdx.x;
    const int lane = tid & 31;
    const int wid = tid >> 5;

    for (int i = tid; i < 8192; i += 1024) {
        if (i < NANCH) {
            u32 sbits = __float_as_uint(g_scores[i]);   // (0,1): order-preserving bits
            sk[i] = ((ULL)sbits << 32) | (ULL)(0xFFFFFFFFu - (u32)i);
        } else {
            sk[i] = 0ull;
        }
    }
    __syncthreads();

    // Phase A: k = 2..32 entirely in-warp
    for (int r = wid; r < 256; r += 32) {
        const int base = r * 32;
        const int i = base + lane;
        ULL key = sk[i];
#pragma unroll
        for (int k = 2; k <= 32; k <<= 1)
#pragma unroll
            for (int j = k >> 1; j > 0; j >>= 1)
                key = warp_cx(key, lane, i, j, k);
        sk[i] = key;
    }
    __syncthreads();

    // Phase B: k = 64..8192
    for (int k = 64; k <= 8192; k <<= 1) {
        for (int j = k >> 1; j >= 32; j >>= 1) {
#pragma unroll
            for (int u = 0; u < 4; u++) {
                int t = u * 1024 + tid;
                int i = ((t & ~(j - 1)) << 1) | (t & (j - 1));
                int l = i | j;
                bool desc = ((i & k) == 0);
                ULL a = sk[i], b = sk[l];
                if (desc ? (a < b) : (a > b)) { sk[i] = b; sk[l] = a; }
            }
            __syncthreads();
        }
        for (int r = wid; r < 256; r += 32) {
            const int base = r * 32;
            const int i = base + lane;
            ULL key = sk[i];
#pragma unroll
            for (int j = 16; j > 0; j >>= 1)
                key = warp_cx(key, lane, i, j, k);
            sk[i] = key;
        }
        __syncthreads();
    }

    for (int i = tid; i < NANCH; i += 1024) {
        u32 idx = 0xFFFFFFFFu - (u32)(sk[i] & 0xFFFFFFFFull);
        g_boxes_sorted[i] = g_boxes[idx];
    }
}

// =====================================================================
// Kernel 4: pairwise suppression mask, FULLY PARALLEL.
// grid (125, 125), 128 threads.
// =====================================================================
__global__ __launch_bounds__(128) void mask_build()
{
    const int bx = blockIdx.x, by = blockIdx.y;
    const int tid = threadIdx.x;
    const int i_loc = tid >> 1, wsel = tid & 1;
    const int ig = by * 64 + i_loc;

    if (bx < by) {
        g_mask[(size_t)ig * NWORDS + bx * 2 + wsel] = 0u;
        return;
    }

    __shared__ float4 rb[64]; __shared__ float ra[64];
    __shared__ float4 cb[64]; __shared__ float ca[64];
    if (tid < 64) {
        float4 b = g_boxes_sorted[by * 64 + tid];
        rb[tid] = b; ra[tid] = (b.z - b.x) * (b.w - b.y);
    } else {
        int t = tid - 64;
        float4 b = g_boxes_sorted[bx * 64 + t];
        cb[t] = b; ca[t] = (b.z - b.x) * (b.w - b.y);
    }
    __syncthreads();

    const float4 kb = rb[i_loc];
    const float areaK = ra[i_loc];
    u32 bits = 0;

#pragma unroll 4
    for (int jl = wsel * 32; jl < wsel * 32 + 32; jl++) {
        int jg = bx * 64 + jl;
        if (jg <= ig) continue;
        float4 bb = cb[jl];
        float iw = fminf(kb.z, bb.z) - fmaxf(kb.x, bb.x);
        float ih = fminf(kb.w, bb.w) - fmaxf(kb.y, bb.y);
        if (iw > 0.f && ih > 0.f) {
            float inter = iw * ih;
            float uni = areaK + ca[jl] - inter;
            float d = __fmaf_rn(-0.7f, uni, inter);
            bool kill;
            if (fabsf(d) >= 1e-5f * uni) {
                kill = (d >= 0.f);
            } else {
                kill = (__fdiv_rn(inter, uni) >= 0.7f);   // exact, rare
            }
            if (kill) bits |= (1u << (jl & 31));
        }
    }
    g_mask[(size_t)ig * NWORDS + bx * 2 + wsel] = bits;
}

// =====================================================================
// Kernel 5: BATCHED serial scan.  1 block, 256 threads.
// =====================================================================
__global__ void nms_scan()
{
    __shared__ u32 remv[NWORDS];
    __shared__ u32 rows[NMSBATCH][NWORDS];
    __shared__ int s_cand[NMSBATCH];
    __shared__ int s_nc, s_kc;
    const int tid = threadIdx.x;

    if (tid < NWORDS) remv[tid] = 0u;
    if (tid == 0) s_kc = 0;
    int cur = 0;
    __syncthreads();

    while (true) {
        if (tid == 0) {
            int nc = 0;
            int w = cur >> 5;
            u32 m = (w < NWORDS) ? ((~remv[w]) & (0xFFFFFFFFu << (cur & 31))) : 0u;
            while (nc < NMSBATCH && w < NWORDS) {
                if (m) {
                    int b = __ffs(m) - 1;
                    s_cand[nc++] = (w << 5) + b;
                    m &= m - 1;
                } else {
                    if (++w < NWORDS) m = ~remv[w];
                }
            }
            s_nc = nc;
        }
        __syncthreads();
        const int nc = s_nc;
        if (nc == 0 || s_kc >= MAXDET) break;

#pragma unroll
        for (int c = 0; c < NMSBATCH; c++) {
            if (c < nc && tid < NWORDS)
                rows[c][tid] = g_mask[(size_t)s_cand[c] * NWORDS + tid];
        }
        __syncthreads();

        for (int c = 0; c < nc; c++) {
            const int i = s_cand[c];
            const bool alive = !((remv[i >> 5] >> (i & 31)) & 1u);
            const int kc = s_kc;
            __syncthreads();
            if (alive && kc < MAXDET) {
                if (tid == 0) {
                    float4 b = g_boxes_sorted[i];
                    g_rois[kc * 4 + 0] = b.x;
                    g_rois[kc * 4 + 1] = b.y;
                    g_rois[kc * 4 + 2] = b.z;
                    g_rois[kc * 4 + 3] = b.w;
                    s_kc = kc + 1;
                }
                if (tid < NWORDS) remv[tid] |= rows[c][tid];
            }
            __syncthreads();
        }
        if (tid == 0) cur = s_cand[nc - 1] + 1;
        __syncthreads();
    }

    const int kc = s_kc;
    const int rem = (MAXDET - kc) * 4;
    for (int e = tid; e < rem; e += 256) g_rois[kc * 4 + e] = 0.f;
}

// =====================================================================
// Kernel 6: FC head + softmax + output. grid 300, 128 threads.
// =====================================================================
__global__ void fc_head(
    const float* __restrict__ fc1_w, const float* __restrict__ fc1_b,
    const float* __restrict__ clsh_w, const float* __restrict__ clsh_b,
    const float* __restrict__ regh_w, const float* __restrict__ regh_b,
    float* __restrict__ out)
{
    const int r = blockIdx.x;
    const int tid = threadIdx.x;
    __shared__ float s_roi[4];
    __shared__ float red[8][128];

    if (tid < 4) s_roi[tid] = g_rois[r * 4 + tid];
    __syncthreads();
    float r0 = s_roi[0], r1 = s_roi[1], r2 = s_roi[2], r3 = s_roi[3];

    float cls[4] = {0.f, 0.f, 0.f, 0.f};
    float reg[4] = {0.f, 0.f, 0.f, 0.f};
    for (int j = tid; j < 1024; j += 128) {
        float fc = r0 * fc1_w[j] + r1 * fc1_w[1024 + j]
                 + r2 * fc1_w[2048 + j] + r3 * fc1_w[3072 + j] + fc1_b[j];
        fc = fmaxf(fc, 0.f);
#pragma unroll
        for (int c = 0; c < 4; c++) {
            cls[c] += fc * clsh_w[j * 4 + c];
            reg[c] += fc * regh_w[j * 4 + c];
        }
    }
#pragma unroll
    for (int c = 0; c < 4; c++) { red[c][tid] = cls[c]; red[4 + c][tid] = reg[c]; }
    __syncthreads();
    for (int s = 64; s > 0; s >>= 1) {
        if (tid < s) {
#pragma unroll
            for (int c = 0; c < 8; c++) red[c][tid] += red[c][tid + s];
        }
        __syncthreads();
    }
    if (tid == 0) {
        float lg[4], mx = -1e30f;
#pragma unroll
        for (int c = 0; c < 4; c++) { lg[c] = red[c][0] + clsh_b[c]; mx = fmaxf(mx, lg[c]); }
        float es[4], sum = 0.f;
#pragma unroll
        for (int c = 0; c < 4; c++) { es[c] = expf(lg[c] - mx); sum += es[c]; }
#pragma unroll
        for (int c = 0; c < 4; c++) {
            out[r * 4 + c]        = es[c] / sum;                 // class_scores
            out[1200 + r * 4 + c] = red[4 + c][0] + regh_b[c];   // box_deltas
            out[2400 + r * 4 + c] = s_roi[c];                    // rois
        }
    }
}

// =====================================================================
extern "C" void kernel_launch(void* const* d_in, const int* in_sizes, int n_in,
                              void* d_out, int out_size)
{
    const float* feat   = (const float*)d_in[0];
    const float* conv_w = (const float*)d_in[1];
    const float* conv_b = (const float*)d_in[2];
    const float* cls_w  = (const float*)d_in[3];
    const float* cls_b  = (const float*)d_in[4];
    const float* reg_w  = (const float*)d_in[5];
    const float* reg_b  = (const float*)d_in[6];
    const float* fc1_w  = (const float*)d_in[7];
    const float* fc1_b  = (const float*)d_in[8];
    const float* clsh_w = (const float*)d_in[9];
    const float* clsh_b = (const float*)d_in[10];
    const float* regh_w = (const float*)d_in[11];
    const float* regh_b = (const float*)d_in[12];
    float* out = (float*)d_out;

    static int smem_set = 0;
    if (!smem_set) {
        cudaFuncSetAttribute(sort_kernel, cudaFuncAttributeMaxDynamicSharedMemorySize, 65536);
        smem_set = 1;
    }

    // 3 nops so the profiler's fixed 4th-launch capture hits the conv
    nop_kernel<<<1, 32>>>();
    nop_kernel<<<1, 32>>>();
    nop_kernel<<<1, 32>>>();
    conv3x3_partial<<<dim3(25, 4, 9), 64>>>(feat, conv_w);
    reduce_heads<<<100, 256>>>(conv_b, cls_w, cls_b, reg_w, reg_b);
    sort_kernel<<<1, 1024, 65536>>>();
    mask_build<<<dim3(125, 125), 128>>>();
    nms_scan<<<1, 256>>>();
    fc_head<<<MAXDET, 128>>>(fc1_w, fc1_b, clsh_w, clsh_b, regh_w, regh_b, out);
}

// round 10
// speedup vs baseline: 1.7223x; 1.7223x over previous
#include <cuda_runtime.h>
#include <cuda_bf16.h>
#include <math.h>
#include <stdint.h>

typedef unsigned long long ULL;
typedef unsigned int u32;

#define H 40
#define W 40
#define CIN 2048
#define CMID 256
#define NPIX 1600
#define NANCH 8000
#define MAXDET 300
#define NWORDS 250          // 8000/32
#define NMSBATCH 8

__device__ __constant__ float c_anchor[5] = {32.f, 64.f, 128.f, 256.f, 512.f};

// ---------------- device scratch (static; no allocation) ----------------
__device__ float  g_featT[CIN * NPIX];          // transposed features [c][p] (13MB)
__device__ float  g_partial[9 * NPIX * CMID];   // per-tap conv partials
__device__ float  g_scores[NANCH];
__device__ float4 g_boxes[NANCH];
__device__ float4 g_boxes_sorted[NANCH];
__device__ u32    g_mask[NANCH * NWORDS];       // suppression bitmap rows (8MB)
__device__ float  g_rois[MAXDET * 4];

__global__ void nop_kernel() {}

// =====================================================================
// Kernel 0: feat [p][c] -> g_featT [c][p], 32x32 smem tiles.
// grid (64, 50), 256 threads.
// =====================================================================
__global__ __launch_bounds__(256) void transpose_feat(const float* __restrict__ feat)
{
    __shared__ float t[32][33];
    const int c0 = blockIdx.x * 32, p0 = blockIdx.y * 32;
    const int tx = threadIdx.x & 31, ty = threadIdx.x >> 5;
#pragma unroll
    for (int i = 0; i < 32; i += 8)
        t[ty + i][tx] = feat[(size_t)(p0 + ty + i) * CIN + c0 + tx];
    __syncthreads();
#pragma unroll
    for (int i = 0; i < 32; i += 8)
        g_featT[(size_t)(c0 + ty + i) * NPIX + p0 + tx] = t[tx][ty + i];
}

// =====================================================================
// Kernel 1: tap-split implicit GEMM.  grid (25, 2, 9), 128 threads.
// Block tile 64 pixels x 128 couts, per-thread 8x8, fma.rn.f32x2.
// A from g_featT (pixel-consecutive -> ~2 lines/warp-LDG);
// B loads row-contiguous (~4 lines/warp-LDG).
// Compute mapping & K order identical to R8 -> bit-identical partials.
// =====================================================================
__global__ __launch_bounds__(128, 3) void conv3x3_partial(const float* __restrict__ w)
{
    const int mt = blockIdx.x, nt = blockIdx.y, tap = blockIdx.z;
    const int dy = tap / 3 - 1, dx = tap % 3 - 1;
    const int m0 = mt * 64, n0 = nt * 128;
    const int tid = threadIdx.x;

    __shared__ float Asf[16][68];    // [k][pixel]
    __shared__ float Bsf[16][132];   // [k][cout]

    // ---- A loader: pixel pl = tid&63 (consecutive), k-rows kh2+2r ----
    const int pl = tid & 63, kh2 = tid >> 6;   // kh2 in {0,1}
    {
    }
    const int p = m0 + pl;
    const int py = p / W, px = p - py * W;
    const int sy = py + dy, sx = px + dx;
    const bool valid = (sx >= 0) && (sx < W) && (sy >= 0) && (sy < H);
    const float* aT = g_featT + (valid ? (sy * W + sx) : 0);

    // ---- B loader: warp = one k-row, 128 consecutive floats ----
    const int blane = tid & 31, brow = tid >> 5;   // brow in {0..3}
    const float* bp = w + ((size_t)(tap * CIN + brow) * CMID) + n0 + blane * 4;

    // ---- compute mapping: 8 m-groups x 16 n-groups (as R8) ----
    const int mg = tid >> 4, ng = tid & 15;

    ULL acc[8][4];
#pragma unroll
    for (int i = 0; i < 8; i++)
#pragma unroll
        for (int j = 0; j < 4; j++) acc[i][j] = 0ull;

    float ar[8];
    float4 br[4];
    // prologue: chunk 0
#pragma unroll
    for (int r = 0; r < 8; r++)
        ar[r] = valid ? aT[(size_t)(kh2 + 2 * r) * NPIX] : 0.f;
#pragma unroll
    for (int j = 0; j < 4; j++)
        br[j] = *(const float4*)(bp + (size_t)(4 * j) * CMID);

    for (int c0 = 0; c0 < CIN; c0 += 16) {
        __syncthreads();
#pragma unroll
        for (int r = 0; r < 8; r++) Asf[kh2 + 2 * r][pl] = ar[r];
#pragma unroll
        for (int j = 0; j < 4; j++)
            *(float4*)&Bsf[brow + 4 * j][blane * 4] = br[j];
        __syncthreads();

        if (c0 + 16 < CIN) {   // prefetch next chunk under compute
            const int cn = c0 + 16;
#pragma unroll
            for (int r = 0; r < 8; r++)
                ar[r] = valid ? aT[(size_t)(cn + kh2 + 2 * r) * NPIX] : 0.f;
#pragma unroll
            for (int j = 0; j < 4; j++)
                br[j] = *(const float4*)(bp + (size_t)(cn + 4 * j) * CMID);
        }

#pragma unroll
        for (int kc = 0; kc < 16; kc++) {
            float4 a0 = *(const float4*)&Asf[kc][mg * 8 + 0];
            float4 a1 = *(const float4*)&Asf[kc][mg * 8 + 4];
            ulonglong2 b03 = *(const ulonglong2*)&Bsf[kc][ng * 8 + 0];
            ulonglong2 b47 = *(const ulonglong2*)&Bsf[kc][ng * 8 + 4];
            ULL bq[4] = {b03.x, b03.y, b47.x, b47.y};
            float am[8] = {a0.x, a0.y, a0.z, a0.w, a1.x, a1.y, a1.z, a1.w};
#pragma unroll
            for (int mm = 0; mm < 8; mm++) {
                u32 au = __float_as_uint(am[mm]);
                ULL a2;
                asm("mov.b64 %0, {%1, %1};" : "=l"(a2) : "r"(au));
#pragma unroll
                for (int q = 0; q < 4; q++)
                    asm("fma.rn.f32x2 %0, %1, %2, %0;"
                        : "+l"(acc[mm][q]) : "l"(a2), "l"(bq[q]));
            }
        }
    }

#pragma unroll
    for (int mm = 0; mm < 8; mm++) {
        int mrow = m0 + mg * 8 + mm;
        size_t base = ((size_t)tap * NPIX + mrow) * CMID + n0 + ng * 8;
        ulonglong2 lo, hi;
        lo.x = acc[mm][0]; lo.y = acc[mm][1];
        hi.x = acc[mm][2]; hi.y = acc[mm][3];
        *(ulonglong2*)&g_partial[base + 0] = lo;
        *(ulonglong2*)&g_partial[base + 4] = hi;
    }
}

// =====================================================================
// Kernel 2: tap-reduce + bias + relu + 1x1 heads + decode, 16 px/block.
// grid 100, 256 threads.
// =====================================================================
__global__ __launch_bounds__(256) void reduce_heads(
    const float* __restrict__ conv_b,
    const float* __restrict__ cls_w, const float* __restrict__ cls_b,
    const float* __restrict__ reg_w, const float* __restrict__ reg_b)
{
    const int px0 = blockIdx.x * 16;
    const int tid = threadIdx.x;
    const int wid = tid >> 5, lid = tid & 31;
    __shared__ float ws[30 * 256];
    __shared__ float xs[16][256];
    __shared__ float ob[16][30];

    for (int idx = tid; idx < 10 * 256; idx += 256) {
        int k = idx / 10, o = idx - k * 10;
        ws[o * 256 + k] = cls_w[idx];
    }
    for (int idx = tid; idx < 20 * 256; idx += 256) {
        int k = idx / 20, o = idx - k * 20;
        ws[(10 + o) * 256 + k] = reg_w[idx];
    }

    for (int e = tid; e < 16 * 256; e += 256) {
        int pp = e >> 8, n = e & 255;
        int pgl = px0 + pp;
        float s = conv_b[n];
#pragma unroll
        for (int t = 0; t < 9; t++)
            s += g_partial[((size_t)t * NPIX + pgl) * CMID + n];
        xs[pp][n] = fmaxf(s, 0.f);
    }
    __syncthreads();

    for (int task = wid; task < 480; task += 8) {
        int pp = task / 30, o = task - pp * 30;
        float bias = (o < 10) ? cls_b[o] : reg_b[o - 10];
        const float* wrow = &ws[o * 256];
        const float* xrow = xs[pp];
        float s = 0.f;
#pragma unroll
        for (int k = lid; k < 256; k += 32)
            s += xrow[k] * wrow[k];
#pragma unroll
        for (int off = 16; off > 0; off >>= 1)
            s += __shfl_xor_sync(0xFFFFFFFFu, s, off);
        if (lid == 0) ob[pp][o] = s + bias;
    }
    __syncthreads();

    if (tid < 80) {
        const int pp = tid / 5, a = tid - pp * 5;
        const int p = px0 + pp;
        float l0 = ob[pp][2 * a], l1 = ob[pp][2 * a + 1];
        float score = 1.f / (1.f + expf(l0 - l1));
        float d0 = ob[pp][10 + 4 * a + 0];
        float d1 = ob[pp][10 + 4 * a + 1];
        float d2 = ob[pp][10 + 4 * a + 2];
        float d3 = ob[pp][10 + 4 * a + 3];
        float px = (float)(p % W), py = (float)(p / W);
        float base = c_anchor[a];
        float bw = expf(d2) * base;
        float bh = expf(d3) * base;
        float xc = px + d0, yc = py + d1;
        g_scores[p * 5 + a] = score;
        g_boxes[p * 5 + a] = make_float4(xc - 0.5f * bw, yc - 0.5f * bh,
                                         xc + 0.5f * bw, yc + 0.5f * bh);
    }
}

// =====================================================================
// Kernel 3: descending bitonic sort, warp-shuffle tail stages.
// =====================================================================
__device__ __forceinline__ ULL warp_cx(ULL key, int lane, int i, int j, int k)
{
    ULL partner = __shfl_xor_sync(0xFFFFFFFFu, key, j);
    bool up = ((lane & j) == 0);
    bool desc = ((i & k) == 0);
    bool take_max = (up == desc);
    ULL mx = key > partner ? key : partner;
    ULL mn = key > partner ? partner : key;
    return take_max ? mx : mn;
}

__global__ void sort_kernel()
{
    extern __shared__ ULL sk[];
    const int tid = threadIdx.x;
    const int lane = tid & 31;
    const int wid = tid >> 5;

    for (int i = tid; i < 8192; i += 1024) {
        if (i < NANCH) {
            u32 sbits = __float_as_uint(g_scores[i]);
            sk[i] = ((ULL)sbits << 32) | (ULL)(0xFFFFFFFFu - (u32)i);
        } else {
            sk[i] = 0ull;
        }
    }
    __syncthreads();

    for (int r = wid; r < 256; r += 32) {
        const int base = r * 32;
        const int i = base + lane;
        ULL key = sk[i];
#pragma unroll
        for (int k = 2; k <= 32; k <<= 1)
#pragma unroll
            for (int j = k >> 1; j > 0; j >>= 1)
                key = warp_cx(key, lane, i, j, k);
        sk[i] = key;
    }
    __syncthreads();

    for (int k = 64; k <= 8192; k <<= 1) {
        for (int j = k >> 1; j >= 32; j >>= 1) {
#pragma unroll
            for (int u = 0; u < 4; u++) {
                int t = u * 1024 + tid;
                int i = ((t & ~(j - 1)) << 1) | (t & (j - 1));
                int l = i | j;
                bool desc = ((i & k) == 0);
                ULL a = sk[i], b = sk[l];
                if (desc ? (a < b) : (a > b)) { sk[i] = b; sk[l] = a; }
            }
            __syncthreads();
        }
        for (int r = wid; r < 256; r += 32) {
            const int base = r * 32;
            const int i = base + lane;
            ULL key = sk[i];
#pragma unroll
            for (int j = 16; j > 0; j >>= 1)
                key = warp_cx(key, lane, i, j, k);
            sk[i] = key;
        }
        __syncthreads();
    }

    for (int i = tid; i < NANCH; i += 1024) {
        u32 idx = 0xFFFFFFFFu - (u32)(sk[i] & 0xFFFFFFFFull);
        g_boxes_sorted[i] = g_boxes[idx];
    }
}

// =====================================================================
// Kernel 4: pairwise suppression mask.  grid (125,125), 128 threads.
// =====================================================================
__global__ __launch_bounds__(128) void mask_build()
{
    const int bx = blockIdx.x, by = blockIdx.y;
    const int tid = threadIdx.x;
    const int i_loc = tid >> 1, wsel = tid & 1;
    const int ig = by * 64 + i_loc;

    if (bx < by) {
        g_mask[(size_t)ig * NWORDS + bx * 2 + wsel] = 0u;
        return;
    }

    __shared__ float4 rb[64]; __shared__ float ra[64];
    __shared__ float4 cb[64]; __shared__ float ca[64];
    if (tid < 64) {
        float4 b = g_boxes_sorted[by * 64 + tid];
        rb[tid] = b; ra[tid] = (b.z - b.x) * (b.w - b.y);
    } else {
        int t = tid - 64;
        float4 b = g_boxes_sorted[bx * 64 + t];
        cb[t] = b; ca[t] = (b.z - b.x) * (b.w - b.y);
    }
    __syncthreads();

    const float4 kb = rb[i_loc];
    const float areaK = ra[i_loc];
    u32 bits = 0;

#pragma unroll 4
    for (int jl = wsel * 32; jl < wsel * 32 + 32; jl++) {
        int jg = bx * 64 + jl;
        if (jg <= ig) continue;
        float4 bb = cb[jl];
        float iw = fminf(kb.z, bb.z) - fmaxf(kb.x, bb.x);
        float ih = fminf(kb.w, bb.w) - fmaxf(kb.y, bb.y);
        if (iw > 0.f && ih > 0.f) {
            float inter = iw * ih;
            float uni = areaK + ca[jl] - inter;
            float d = __fmaf_rn(-0.7f, uni, inter);
            bool kill;
            if (fabsf(d) >= 1e-5f * uni) {
                kill = (d >= 0.f);
            } else {
                kill = (__fdiv_rn(inter, uni) >= 0.7f);
            }
            if (kill) bits |= (1u << (jl & 31));
        }
    }
    g_mask[(size_t)ig * NWORDS + bx * 2 + wsel] = bits;
}

// =====================================================================
// Kernel 5: BATCHED serial scan.  1 block, 256 threads.
// =====================================================================
__global__ void nms_scan()
{
    __shared__ u32 remv[NWORDS];
    __shared__ u32 rows[NMSBATCH][NWORDS];
    __shared__ int s_cand[NMSBATCH];
    __shared__ int s_nc, s_kc;
    const int tid = threadIdx.x;

    if (tid < NWORDS) remv[tid] = 0u;
    if (tid == 0) s_kc = 0;
    int cur = 0;
    __syncthreads();

    while (true) {
        if (tid == 0) {
            int nc = 0;
            int w = cur >> 5;
            u32 m = (w < NWORDS) ? ((~remv[w]) & (0xFFFFFFFFu << (cur & 31))) : 0u;
            while (nc < NMSBATCH && w < NWORDS) {
                if (m) {
                    int b = __ffs(m) - 1;
                    s_cand[nc++] = (w << 5) + b;
                    m &= m - 1;
                } else {
                    if (++w < NWORDS) m = ~remv[w];
                }
            }
            s_nc = nc;
        }
        __syncthreads();
        const int nc = s_nc;
        if (nc == 0 || s_kc >= MAXDET) break;

#pragma unroll
        for (int c = 0; c < NMSBATCH; c++) {
            if (c < nc && tid < NWORDS)
                rows[c][tid] = g_mask[(size_t)s_cand[c] * NWORDS + tid];
        }
        __syncthreads();

        for (int c = 0; c < nc; c++) {
            const int i = s_cand[c];
            const bool alive = !((remv[i >> 5] >> (i & 31)) & 1u);
            const int kc = s_kc;
            __syncthreads();
            if (alive && kc < MAXDET) {
                if (tid == 0) {
                    float4 b = g_boxes_sorted[i];
                    g_rois[kc * 4 + 0] = b.x;
                    g_rois[kc * 4 + 1] = b.y;
                    g_rois[kc * 4 + 2] = b.z;
                    g_rois[kc * 4 + 3] = b.w;
                    s_kc = kc + 1;
                }
                if (tid < NWORDS) remv[tid] |= rows[c][tid];
            }
            __syncthreads();
        }
        if (tid == 0) cur = s_cand[nc - 1] + 1;
        __syncthreads();
    }

    const int kc = s_kc;
    const int rem = (MAXDET - kc) * 4;
    for (int e = tid; e < rem; e += 256) g_rois[kc * 4 + e] = 0.f;
}

// =====================================================================
// Kernel 6: FC head + softmax + output. grid 300, 128 threads.
// =====================================================================
__global__ void fc_head(
    const float* __restrict__ fc1_w, const float* __restrict__ fc1_b,
    const float* __restrict__ clsh_w, const float* __restrict__ clsh_b,
    const float* __restrict__ regh_w, const float* __restrict__ regh_b,
    float* __restrict__ out)
{
    const int r = blockIdx.x;
    const int tid = threadIdx.x;
    __shared__ float s_roi[4];
    __shared__ float red[8][128];

    if (tid < 4) s_roi[tid] = g_rois[r * 4 + tid];
    __syncthreads();
    float r0 = s_roi[0], r1 = s_roi[1], r2 = s_roi[2], r3 = s_roi[3];

    float cls[4] = {0.f, 0.f, 0.f, 0.f};
    float reg[4] = {0.f, 0.f, 0.f, 0.f};
    for (int j = tid; j < 1024; j += 128) {
        float fc = r0 * fc1_w[j] + r1 * fc1_w[1024 + j]
                 + r2 * fc1_w[2048 + j] + r3 * fc1_w[3072 + j] + fc1_b[j];
        fc = fmaxf(fc, 0.f);
#pragma unroll
        for (int c = 0; c < 4; c++) {
            cls[c] += fc * clsh_w[j * 4 + c];
            reg[c] += fc * regh_w[j * 4 + c];
        }
    }
#pragma unroll
    for (int c = 0; c < 4; c++) { red[c][tid] = cls[c]; red[4 + c][tid] = reg[c]; }
    __syncthreads();
    for (int s = 64; s > 0; s >>= 1) {
        if (tid < s) {
#pragma unroll
            for (int c = 0; c < 8; c++) red[c][tid] += red[c][tid + s];
        }
        __syncthreads();
    }
    if (tid == 0) {
        float lg[4], mx = -1e30f;
#pragma unroll
        for (int c = 0; c < 4; c++) { lg[c] = red[c][0] + clsh_b[c]; mx = fmaxf(mx, lg[c]); }
        float es[4], sum = 0.f;
#pragma unroll
        for (int c = 0; c < 4; c++) { es[c] = expf(lg[c] - mx); sum += es[c]; }
#pragma unroll
        for (int c = 0; c < 4; c++) {
            out[r * 4 + c]        = es[c] / sum;                 // class_scores
            out[1200 + r * 4 + c] = red[4 + c][0] + regh_b[c];   // box_deltas
            out[2400 + r * 4 + c] = s_roi[c];                    // rois
        }
    }
}

// =====================================================================
extern "C" void kernel_launch(void* const* d_in, const int* in_sizes, int n_in,
                              void* d_out, int out_size)
{
    const float* feat   = (const float*)d_in[0];
    const float* conv_w = (const float*)d_in[1];
    const float* conv_b = (const float*)d_in[2];
    const float* cls_w  = (const float*)d_in[3];
    const float* cls_b  = (const float*)d_in[4];
    const float* reg_w  = (const float*)d_in[5];
    const float* reg_b  = (const float*)d_in[6];
    const float* fc1_w  = (const float*)d_in[7];
    const float* fc1_b  = (const float*)d_in[8];
    const float* clsh_w = (const float*)d_in[9];
    const float* clsh_b = (const float*)d_in[10];
    const float* regh_w = (const float*)d_in[11];
    const float* regh_b = (const float*)d_in[12];
    float* out = (float*)d_out;

    static int smem_set = 0;
    if (!smem_set) {
        cudaFuncSetAttribute(sort_kernel, cudaFuncAttributeMaxDynamicSharedMemorySize, 65536);
        smem_set = 1;
    }

    // launch #4 = conv (profiler captures the 4th launch)
    transpose_feat<<<dim3(64, 50), 256>>>(feat);
    nop_kernel<<<1, 32>>>();
    nop_kernel<<<1, 32>>>();
    conv3x3_partial<<<dim3(25, 2, 9), 128>>>(conv_w);
    reduce_heads<<<100, 256>>>(conv_b, cls_w, cls_b, reg_w, reg_b);
    sort_kernel<<<1, 1024, 65536>>>();
    mask_build<<<dim3(125, 125), 128>>>();
    nms_scan<<<1, 256>>>();
    fc_head<<<MAXDET, 128>>>(fc1_w, fc1_b, clsh_w, clsh_b, regh_w, regh_b, out);
}